// round 2
// baseline (speedup 1.0000x reference)
#include <cuda_runtime.h>
#include <math.h>

#define D 128
#define G 256
#define BMAX 8192
#define CHUNK 32   // nodes per warp

__device__ float g_w[D];        // Wp @ We[:G]
__device__ float g_c;           // bp . We[:G]
__device__ float g_accum[BMAX]; // zero at module load; finalize re-zeroes after use

// ---------------------------------------------------------------------------
// Kernel 1: fold Wp/bp into We's graph-embed half.
// warps 0..127 compute g_w[warp]; warp 128 -> g_c.  (129 warps = 4128 threads)
// ---------------------------------------------------------------------------
__global__ void dgmg_precompute(const float* __restrict__ Wp,
                                const float* __restrict__ bp,
                                const float* __restrict__ We) {
    int gt   = blockIdx.x * blockDim.x + threadIdx.x;
    int gw   = gt >> 5;
    int lane = gt & 31;
    if (gw < D) {
        const float* row = Wp + (size_t)gw * G;
        float s = 0.0f;
        #pragma unroll
        for (int i = 0; i < G / 32; i++) {
            int idx = lane + 32 * i;
            s += row[idx] * We[idx];
        }
        #pragma unroll
        for (int off = 16; off > 0; off >>= 1)
            s += __shfl_xor_sync(0xffffffffu, s, off);
        if (lane == 0) g_w[gw] = s;
    } else if (gw == D) {
        float s = 0.0f;
        #pragma unroll
        for (int i = 0; i < G / 32; i++) {
            int idx = lane + 32 * i;
            s += bp[idx] * We[idx];
        }
        #pragma unroll
        for (int off = 16; off > 0; off >>= 1)
            s += __shfl_xor_sync(0xffffffffu, s, off);
        if (lane == 0) g_c = s;
    }
}

// ---------------------------------------------------------------------------
// Kernel 2: stream hv once. One warp handles CHUNK consecutive nodes with a
// depth-2 software pipeline so the next rows' loads are in flight while the
// current row's shuffle-reduce chain runs. Sorted seg_ids -> run-length
// aggregation in registers, atomicAdd only at run boundaries.
// ---------------------------------------------------------------------------
__global__ void __launch_bounds__(256)
dgmg_node_pass(const float* __restrict__ hv,
               const float* __restrict__ Wg,
               const float* __restrict__ bg,
               const int*   __restrict__ seg,
               int N) {
    const int lane = threadIdx.x & 31;
    const int wid  = blockIdx.x * (blockDim.x >> 5) + (threadIdx.x >> 5);

    const int start = wid * CHUNK;
    if (start >= N) return;
    const int cnt = min(CHUNK, N - start);

    const float  bg0 = bg[0];
    const float  c0  = g_c;
    const float4 wg4 = reinterpret_cast<const float4*>(Wg)[lane];
    const float4 w4  = reinterpret_cast<const float4*>(g_w)[lane];

    // one coalesced load of this chunk's segment ids
    const int segv = seg[min(start + lane, N - 1)];

    const float4* hrow = reinterpret_cast<const float4*>(hv) + (size_t)start * 32 + lane;

    // depth-2 prefetch pipeline
    float4 h0 = __ldcs(hrow);
    float4 h1 = (cnt > 1) ? __ldcs(hrow + 32) : h0;

    int   cur_seg = __shfl_sync(0xffffffffu, segv, 0);
    float acc     = 0.0f;

    #pragma unroll 4
    for (int i = 0; i < cnt; i++) {
        const float4 h = h0;
        h0 = h1;
        if (i + 2 < cnt) h1 = __ldcs(hrow + (size_t)(i + 2) * 32);

        float d1 = h.x * wg4.x + h.y * wg4.y + h.z * wg4.z + h.w * wg4.w;
        float d2 = h.x * w4.x  + h.y * w4.y  + h.z * w4.z  + h.w * w4.w;
        #pragma unroll
        for (int off = 16; off > 0; off >>= 1) {
            d1 += __shfl_xor_sync(0xffffffffu, d1, off);
            d2 += __shfl_xor_sync(0xffffffffu, d2, off);
        }

        const float gate    = 1.0f / (1.0f + expf(-(d1 + bg0)));
        const float contrib = gate * (d2 + c0);

        const int s_id = __shfl_sync(0xffffffffu, segv, i);
        if (s_id != cur_seg) {
            if (lane == 0) atomicAdd(&g_accum[cur_seg], acc);
            acc     = 0.0f;
            cur_seg = s_id;
        }
        acc += contrib;
    }
    if (lane == 0) atomicAdd(&g_accum[cur_seg], acc);
}

// ---------------------------------------------------------------------------
// Kernel 3: one warp per graph. Gather src embedding, dot with We[G:],
// combine with accumulated graph term, stable log-sigmoid, pick by action a.
// Re-zeroes g_accum[b] afterward so the next graph replay starts clean
// (g_accum is zero-initialized at module load for the first call).
// ---------------------------------------------------------------------------
__global__ void __launch_bounds__(256)
dgmg_finalize(const float* __restrict__ hv,
              const float* __restrict__ We,
              const float* __restrict__ be,
              const int*   __restrict__ last_idx,
              const int*   __restrict__ a,
              float*       __restrict__ out,
              int B) {
    const int lane = threadIdx.x & 31;
    const int b = blockIdx.x * (blockDim.x >> 5) + (threadIdx.x >> 5);
    if (b >= B) return;

    const int li = last_idx[b];
    const float4 h  = reinterpret_cast<const float4*>(hv + (size_t)li * D)[lane];
    const float4 we = reinterpret_cast<const float4*>(We + G)[lane];

    float d = h.x * we.x + h.y * we.y + h.z * we.z + h.w * we.w;
    #pragma unroll
    for (int off = 16; off > 0; off >>= 1)
        d += __shfl_xor_sync(0xffffffffu, d, off);

    if (lane == 0) {
        float logit = g_accum[b] + d + be[0];
        g_accum[b] = 0.0f;   // reset for next replay
        float x = (a[b] != 0) ? logit : -logit;
        float ls = (x >= 0.0f) ? -log1pf(expf(-x)) : (x - log1pf(expf(x)));
        out[b] = ls;
    }
}

// ---------------------------------------------------------------------------
extern "C" void kernel_launch(void* const* d_in, const int* in_sizes, int n_in,
                              void* d_out, int out_size) {
    const float* hv       = (const float*)d_in[0];
    const float* Wg       = (const float*)d_in[1];
    const float* bg       = (const float*)d_in[2];
    const float* Wp       = (const float*)d_in[3];
    const float* bp       = (const float*)d_in[4];
    const float* We       = (const float*)d_in[5];
    const float* be       = (const float*)d_in[6];
    const int*   seg_ids  = (const int*)d_in[7];
    const int*   last_idx = (const int*)d_in[8];
    const int*   a        = (const int*)d_in[9];
    float* out = (float*)d_out;

    const int N = in_sizes[0] / D;
    const int B = in_sizes[8];

    // K1: fold weights (129 warps)
    dgmg_precompute<<<17, 256>>>(Wp, bp, We);

    // K2: node streaming pass (8 warps/block, CHUNK nodes/warp)
    int warps  = (N + CHUNK - 1) / CHUNK;
    int blocks = (warps + 7) / 8;
    dgmg_node_pass<<<blocks, 256>>>(hv, Wg, bg, seg_ids, N);

    // K3: per-graph finalize (8 warps/block)
    int fblocks = (B + 7) / 8;
    dgmg_finalize<<<fblocks, 256>>>(hv, We, be, last_idx, a, out, B);
}

// round 3
// speedup vs baseline: 1.0925x; 1.0925x over previous
#include <cuda_runtime.h>
#include <math.h>

#define D 128
#define G 256
#define BMAX 8192
#define CHUNK 8   // nodes per warp, fully front-batched loads

__device__ float g_w[D];        // Wp @ We[:G]
__device__ float g_c;           // bp . We[:G]
__device__ float g_accum[BMAX]; // zero at module load; finalize re-zeroes after use

// ---------------------------------------------------------------------------
// Kernel 1: fold Wp/bp into We's graph-embed half.
// warps 0..127 -> g_w[warp]; warp 128 -> g_c.
// ---------------------------------------------------------------------------
__global__ void dgmg_precompute(const float* __restrict__ Wp,
                                const float* __restrict__ bp,
                                const float* __restrict__ We) {
    int gt   = blockIdx.x * blockDim.x + threadIdx.x;
    int gw   = gt >> 5;
    int lane = gt & 31;
    if (gw < D) {
        const float* row = Wp + (size_t)gw * G;
        float s = 0.0f;
        #pragma unroll
        for (int i = 0; i < G / 32; i++) {
            int idx = lane + 32 * i;
            s += row[idx] * We[idx];
        }
        #pragma unroll
        for (int off = 16; off > 0; off >>= 1)
            s += __shfl_xor_sync(0xffffffffu, s, off);
        if (lane == 0) g_w[gw] = s;
    } else if (gw == D) {
        float s = 0.0f;
        #pragma unroll
        for (int i = 0; i < G / 32; i++) {
            int idx = lane + 32 * i;
            s += bp[idx] * We[idx];
        }
        #pragma unroll
        for (int off = 16; off > 0; off >>= 1)
            s += __shfl_xor_sync(0xffffffffu, s, off);
        if (lane == 0) g_c = s;
    }
}

// ---------------------------------------------------------------------------
// Kernel 2: stream hv once. One warp = CHUNK consecutive nodes.
// ALL row loads are issued up-front as independent LDG.128 (MLP_p1 = 8),
// then the compute/reduce phase runs, then <=2 boundary atomics.
// ---------------------------------------------------------------------------
__global__ void __launch_bounds__(256)
dgmg_node_pass(const float* __restrict__ hv,
               const float* __restrict__ Wg,
               const float* __restrict__ bg,
               const int*   __restrict__ seg,
               int N) {
    const int lane = threadIdx.x & 31;
    const int wid  = blockIdx.x * (blockDim.x >> 5) + (threadIdx.x >> 5);

    const int start = wid * CHUNK;
    if (start >= N) return;
    const int cnt = min(CHUNK, N - start);

    // front-batched independent loads: 8 rows + seg ids + weights
    const float4* hv4 = reinterpret_cast<const float4*>(hv);
    float4 r[CHUNK];
    #pragma unroll
    for (int j = 0; j < CHUNK; j++) {
        int n = min(start + j, N - 1);
        r[j] = __ldg(hv4 + (size_t)n * 32 + lane);
    }
    const int    segv = __ldg(seg + min(start + (lane & (CHUNK - 1)), N - 1));
    const float4 wg4  = reinterpret_cast<const float4*>(Wg)[lane];
    const float4 w4   = reinterpret_cast<const float4*>(g_w)[lane];
    const float  bg0  = __ldg(bg);
    const float  c0   = g_c;

    int   cur_seg = __shfl_sync(0xffffffffu, segv, 0);
    float acc     = 0.0f;

    #pragma unroll
    for (int j = 0; j < CHUNK; j++) {
        const float4 h = r[j];
        float d1 = h.x * wg4.x + h.y * wg4.y + h.z * wg4.z + h.w * wg4.w;
        float d2 = h.x * w4.x  + h.y * w4.y  + h.z * w4.z  + h.w * w4.w;
        #pragma unroll
        for (int off = 16; off > 0; off >>= 1) {
            d1 += __shfl_xor_sync(0xffffffffu, d1, off);
            d2 += __shfl_xor_sync(0xffffffffu, d2, off);
        }

        const float gate    = 1.0f / (1.0f + __expf(-(d1 + bg0)));
        const float contrib = gate * (d2 + c0);
        const int   s_id    = __shfl_sync(0xffffffffu, segv, j);

        if (j < cnt) {
            if (s_id != cur_seg) {
                if (lane == 0) atomicAdd(&g_accum[cur_seg], acc);
                acc     = 0.0f;
                cur_seg = s_id;
            }
            acc += contrib;
        }
    }
    if (lane == 0) atomicAdd(&g_accum[cur_seg], acc);
}

// ---------------------------------------------------------------------------
// Kernel 3: one warp per graph. Gather src embedding, dot with We[G:],
// combine with accumulated graph term, stable log-sigmoid, pick by a.
// Re-zeroes g_accum[b] so the next graph replay starts clean.
// ---------------------------------------------------------------------------
__global__ void __launch_bounds__(256)
dgmg_finalize(const float* __restrict__ hv,
              const float* __restrict__ We,
              const float* __restrict__ be,
              const int*   __restrict__ last_idx,
              const int*   __restrict__ a,
              float*       __restrict__ out,
              int B) {
    const int lane = threadIdx.x & 31;
    const int b = blockIdx.x * (blockDim.x >> 5) + (threadIdx.x >> 5);
    if (b >= B) return;

    const int li = __ldg(last_idx + b);
    const float4 h  = reinterpret_cast<const float4*>(hv + (size_t)li * D)[lane];
    const float4 we = reinterpret_cast<const float4*>(We + G)[lane];

    float d = h.x * we.x + h.y * we.y + h.z * we.z + h.w * we.w;
    #pragma unroll
    for (int off = 16; off > 0; off >>= 1)
        d += __shfl_xor_sync(0xffffffffu, d, off);

    if (lane == 0) {
        float logit = g_accum[b] + d + be[0];
        g_accum[b] = 0.0f;   // reset for next replay
        float x = (a[b] != 0) ? logit : -logit;
        float ls = (x >= 0.0f) ? -log1pf(expf(-x)) : (x - log1pf(expf(x)));
        out[b] = ls;
    }
}

// ---------------------------------------------------------------------------
extern "C" void kernel_launch(void* const* d_in, const int* in_sizes, int n_in,
                              void* d_out, int out_size) {
    const float* hv       = (const float*)d_in[0];
    const float* Wg       = (const float*)d_in[1];
    const float* bg       = (const float*)d_in[2];
    const float* Wp       = (const float*)d_in[3];
    const float* bp       = (const float*)d_in[4];
    const float* We       = (const float*)d_in[5];
    const float* be       = (const float*)d_in[6];
    const int*   seg_ids  = (const int*)d_in[7];
    const int*   last_idx = (const int*)d_in[8];
    const int*   a        = (const int*)d_in[9];
    float* out = (float*)d_out;

    const int N = in_sizes[0] / D;
    const int B = in_sizes[8];

    // K1: fold weights (129 warps)
    dgmg_precompute<<<17, 256>>>(Wp, bp, We);

    // K2: node streaming pass (8 warps/block, CHUNK nodes/warp, front-batched)
    int warps  = (N + CHUNK - 1) / CHUNK;
    int blocks = (warps + 7) / 8;
    dgmg_node_pass<<<blocks, 256>>>(hv, Wg, bg, seg_ids, N);

    // K3: per-graph finalize (8 warps/block)
    int fblocks = (B + 7) / 8;
    dgmg_finalize<<<fblocks, 256>>>(hv, We, be, last_idx, a, out, B);
}